// round 14
// baseline (speedup 1.0000x reference)
#include <cuda_runtime.h>
#include <cuda_fp16.h>
#include <cstdint>

#define K_DIM 1024
#define M_DIM 2048
#define N_DIM 1024
#define NCHUNK 64
#define NCTA   296

// Operands stored in m16n8k16 fragment order (identical to R8).
__device__ uint4 g_Ahi[(size_t)NCHUNK * 128 * 32];
__device__ uint4 g_Alo[(size_t)NCHUNK * 128 * 32];
__device__ uint4 g_Bfr[(size_t)NCHUNK * 128 * 32];

// ---------------------------------------------------------------------------
__global__ void zero_out_kernel(float4* __restrict__ out) {
    out[blockIdx.x * 256 + threadIdx.x] = make_float4(0.f, 0.f, 0.f, 0.f);
}

// ---------------------------------------------------------------------------
// Fused prep (identical to R8): blocks [0,512) do X, [512,768) do W.
// ---------------------------------------------------------------------------
__global__ void prep_kernel(const float* __restrict__ X,
                            const float* __restrict__ W,
                            const float* __restrict__ vmap,
                            const float* __restrict__ wmap) {
    __shared__ float s_lut[256];
    __shared__ unsigned sHi[256][9];
    __shared__ unsigned sLo[256][9];

    const int tid = threadIdx.x;
    const bool isX = blockIdx.x < 512;
    s_lut[tid] = isX ? vmap[tid] : wmap[tid];
    __syncthreads();

    unsigned hi[8], lo[8];
    if (isX) {
        const int b = blockIdx.x;
        const int r = b >> 3, m0b = (b & 7) * 256;
        const int m = m0b + tid;
        const float* src = X + (size_t)m * K_DIM + r * 16;
        float xs[16];
        ((float4*)xs)[0] = ((const float4*)src)[0];
        ((float4*)xs)[1] = ((const float4*)src)[1];
        ((float4*)xs)[2] = ((const float4*)src)[2];
        ((float4*)xs)[3] = ((const float4*)src)[3];
#pragma unroll
        for (int jj = 0; jj < 8; jj++) {
            unsigned short h[2], l[2];
#pragma unroll
            for (int e = 0; e < 2; e++) {
                int j = 2 * jj + e;
                float xv = xs[j];
                int idx = (int)(xv + 8.0f);
                idx = idx < 0 ? 0 : (idx > 15 ? 15 : idx);
                float xc = (xv + s_lut[j * 16 + idx]) * 0.0625f;
                __half hh = __float2half_rn(xc);
                __half ll = __float2half_rn(xc - __half2float(hh));
                h[e] = __half_as_ushort(hh);
                l[e] = __half_as_ushort(ll);
            }
            hi[jj] = h[0] | ((unsigned)h[1] << 16);
            lo[jj] = l[0] | ((unsigned)l[1] << 16);
        }
#pragma unroll
        for (int jj = 0; jj < 8; jj++) { sHi[tid][jj] = hi[jj]; sLo[tid][jj] = lo[jj]; }
        __syncthreads();

#pragma unroll
        for (int ss = 0; ss < 2; ss++) {
            int s = tid + 256 * ss;
            int f = s >> 5, l = s & 31, g = l >> 2, tq = l & 3;
            int r0 = f * 16 + g, r1 = r0 + 8;
            uint4 H = make_uint4(sHi[r0][tq], sHi[r1][tq], sHi[r0][tq + 4], sHi[r1][tq + 4]);
            uint4 L = make_uint4(sLo[r0][tq], sLo[r1][tq], sLo[r0][tq + 4], sLo[r1][tq + 4]);
            size_t gi = ((size_t)r * 128 + (m0b >> 4) + f) * 32 + l;
            g_Ahi[gi] = H;
            g_Alo[gi] = L;
        }
    } else {
        const int b = blockIdx.x - 512;
        const int r = b >> 2, n0b = (b & 3) * 256;
        const int n = n0b + tid;
#pragma unroll
        for (int jj = 0; jj < 8; jj++) {
            unsigned short h[2], l[2];
#pragma unroll
            for (int e = 0; e < 2; e++) {
                int j = 2 * jj + e;
                float w = W[(size_t)(16 * r + j) * N_DIM + n];
                int idx = (int)(w + 8.0f);
                idx = idx < 0 ? 0 : (idx > 15 ? 15 : idx);
                float wc = w + s_lut[j * 16 + idx];
                __half hh = __float2half_rn(wc);
                __half ll = __float2half_rn(wc - __half2float(hh));
                h[e] = __half_as_ushort(hh);
                l[e] = __half_as_ushort(ll);
            }
            hi[jj] = h[0] | ((unsigned)h[1] << 16);
            lo[jj] = l[0] | ((unsigned)l[1] << 16);
        }
#pragma unroll
        for (int jj = 0; jj < 8; jj++) { sHi[tid][jj] = hi[jj]; sLo[tid][jj] = lo[jj]; }
        __syncthreads();

#pragma unroll
        for (int ss = 0; ss < 4; ss++) {
            int s = tid + 256 * ss;
            int f = s >> 5, l = s & 31, g = l >> 2, tq = l & 3;
            int nl = f * 8 + g;
            uint4 V = make_uint4(sHi[nl][tq], sHi[nl][tq + 4], sLo[nl][tq], sLo[nl][tq + 4]);
            g_Bfr[((size_t)r * 128 + (n0b >> 3) + f) * 32 + l] = V;
        }
    }
}

// ---------------------------------------------------------------------------
#define MMA_INIT(C, A, B0, B1, Z)                                              \
    asm("mma.sync.aligned.m16n8k16.row.col.f32.f16.f16.f32 "                   \
        "{%0,%1,%2,%3}, {%4,%5,%6,%7}, {%8,%9}, {%10,%10,%10,%10};"            \
        : "=f"((C)[0]), "=f"((C)[1]), "=f"((C)[2]), "=f"((C)[3])               \
        : "r"((A).x), "r"((A).y), "r"((A).z), "r"((A).w), "r"(B0), "r"(B1),    \
          "f"(Z))

#define MMA_ACC(C, A, B0, B1)                                                  \
    asm("mma.sync.aligned.m16n8k16.row.col.f32.f16.f16.f32 "                   \
        "{%0,%1,%2,%3}, {%4,%5,%6,%7}, {%8,%9}, {%0,%1,%2,%3};"                \
        : "+f"((C)[0]), "+f"((C)[1]), "+f"((C)[2]), "+f"((C)[3])               \
        : "r"((A).x), "r"((A).y), "r"((A).z), "r"((A).w), "r"(B0), "r"(B1))

// ---------------------------------------------------------------------------
// Main: balanced persistent quarter-jobs. 296 CTAs; CTA c runs jobs
// {c, c+296, c+592, (+888 if c<136)}; job = (tile, 16-chunk quarter).
// Inner loop STATIC (16 chunks, unrolled, literal buffer indices).
// Per-job flush: atomicAdd of exact integers. R8 warp structure otherwise.
// ---------------------------------------------------------------------------
__global__ void __launch_bounds__(256, 2)
opu_main_kernel(float* __restrict__ out) {
    const int t = threadIdx.x, wid = t >> 5, lane = t & 31;
    const int wm = (wid >> 1) * 32, wn = (wid & 1) * 32;
    const int c = blockIdx.x;
    const int njobs = (c < 136) ? 4 : 3;

    const float FZ = 0.0f;
    const float MAGIC = 12582912.0f;     // 1.5*2^23
    const size_t CSTR = 128 * 32;

    for (int jj = 0; jj < njobs; jj++) {
        const int job = c + jj * NCTA;
        const int tile = job >> 2;
        const int c0 = (job & 3) * 16;

        const int m0 = (tile >> 4) * 128, n0 = (tile & 15) * 64;
        const int mf = (m0 + wm) >> 4;
        const int nf = (n0 + wn) >> 3;
        const uint4* pA0 = g_Ahi + (size_t)mf * 32 + lane;
        const uint4* pA1 = g_Alo + (size_t)mf * 32 + lane;
        const uint4* pB  = g_Bfr + (size_t)nf * 32 + lane;

        unsigned su[2][4][4];
#pragma unroll
        for (int i = 0; i < 2; i++)
#pragma unroll
            for (int j = 0; j < 4; j++)
#pragma unroll
                for (int e = 0; e < 4; e++) su[i][j][e] = 0u;

        uint4 AH[2][2], AL[2][2], BF[2][4];

#define LOAD_CHUNK(buf, r)                                                     \
        do {                                                                   \
            const size_t o = (size_t)(r) * CSTR;                               \
            AH[buf][0] = pA0[o];        AH[buf][1] = pA0[o + 32];              \
            AL[buf][0] = pA1[o];        AL[buf][1] = pA1[o + 32];              \
            BF[buf][0] = pB[o];         BF[buf][1] = pB[o + 32];               \
            BF[buf][2] = pB[o + 64];    BF[buf][3] = pB[o + 96];               \
        } while (0)

#define COMPUTE_CHUNK(buf)                                                     \
        do {                                                                   \
            _Pragma("unroll")                                                  \
            for (int i = 0; i < 2; i++) {                                      \
                _Pragma("unroll")                                              \
                for (int jp = 0; jp < 2; jp++) {                               \
                    float a0[4], a1[4];                                        \
                    const uint4 b0 = BF[buf][2 * jp], b1 = BF[buf][2 * jp + 1];\
                    MMA_INIT(a0, AH[buf][i], b0.x, b0.y, FZ);                  \
                    MMA_INIT(a1, AH[buf][i], b1.x, b1.y, FZ);                  \
                    MMA_ACC(a0, AH[buf][i], b0.z, b0.w);                       \
                    MMA_ACC(a1, AH[buf][i], b1.z, b1.w);                       \
                    MMA_ACC(a0, AL[buf][i], b0.x, b0.y);                       \
                    MMA_ACC(a1, AL[buf][i], b1.x, b1.y);                       \
                    _Pragma("unroll")                                          \
                    for (int e = 0; e < 4; e++) {                              \
                        su[i][2 * jp][e]     += __float_as_uint(a0[e] + MAGIC);\
                        su[i][2 * jp + 1][e] += __float_as_uint(a1[e] + MAGIC);\
                    }                                                          \
                }                                                              \
            }                                                                  \
        } while (0)

        LOAD_CHUNK(0, c0);
#pragma unroll
        for (int r = 0; r < 16; r += 2) {
            LOAD_CHUNK(1, c0 + r + 1);
            COMPUTE_CHUNK(0);
            LOAD_CHUNK(0, (r + 2 < 16) ? (c0 + r + 2) : c0);   // static idx, harmless tail reload
            COMPUTE_CHUNK(1);
        }

        // flush: value = 16 * (su - 16*0x4B400000 mod 2^32) ; exact integers
        const unsigned BIAS16 = 0xB4000000u;   // 16 * 0x4B400000 mod 2^32
        const int g = lane >> 2, tg = lane & 3;
#pragma unroll
        for (int i = 0; i < 2; i++)
#pragma unroll
            for (int h = 0; h < 2; h++) {
                int row = m0 + wm + 16 * i + 8 * h + g;
                float* orow = out + (size_t)row * N_DIM + n0 + wn + 2 * tg;
#pragma unroll
                for (int j = 0; j < 4; j++) {
                    atomicAdd(orow + 8 * j,
                              16.0f * (float)(int)(su[i][j][2 * h + 0] - BIAS16));
                    atomicAdd(orow + 8 * j + 1,
                              16.0f * (float)(int)(su[i][j][2 * h + 1] - BIAS16));
                }
            }
#undef LOAD_CHUNK
#undef COMPUTE_CHUNK
    }
}

// ---------------------------------------------------------------------------
extern "C" void kernel_launch(void* const* d_in, const int* in_sizes, int n_in,
                              void* d_out, int out_size) {
    const float* X    = (const float*)d_in[0];  // (2,1024,1024)
    const float* W    = (const float*)d_in[1];  // (1024,1024)
    const float* vmap = (const float*)d_in[2];  // (16,16)
    const float* wmap = (const float*)d_in[3];  // (16,16)
    float* out = (float*)d_out;                 // (2,1024,1024)

    zero_out_kernel<<<2048, 256>>>((float4*)out);   // 2048*256 float4 = 2M floats
    prep_kernel<<<768, 256>>>(X, W, vmap, wmap);
    opu_main_kernel<<<NCTA, 256>>>(out);
}

// round 15
// speedup vs baseline: 1.0714x; 1.0714x over previous
#include <cuda_runtime.h>
#include <cuda_fp16.h>
#include <cstdint>

#define K_DIM 1024
#define M_DIM 2048
#define N_DIM 1024
#define NCHUNK 64
#define NCTA_MAIN 444
#define NJOBS 1024

// Operands stored in m16n8k16 fragment order (identical to R8).
__device__ uint4 g_Ahi[(size_t)NCHUNK * 128 * 32];
__device__ uint4 g_Alo[(size_t)NCHUNK * 128 * 32];
__device__ uint4 g_Bfr[(size_t)NCHUNK * 128 * 32];

// ---------------------------------------------------------------------------
// Fused prep (R8) + output zeroing folded in. 768 blocks x 256.
// ---------------------------------------------------------------------------
__global__ void prep_kernel(const float* __restrict__ X,
                            const float* __restrict__ W,
                            const float* __restrict__ vmap,
                            const float* __restrict__ wmap,
                            float4* __restrict__ outz) {
    __shared__ float s_lut[256];
    __shared__ unsigned sHi[256][9];
    __shared__ unsigned sLo[256][9];

    const int tid = threadIdx.x;
    const int gid = blockIdx.x * 256 + tid;           // 0..196607
    const float4 z = make_float4(0.f, 0.f, 0.f, 0.f);
    outz[gid] = z;
    outz[gid + 196608] = z;
    if (gid + 393216 < 524288) outz[gid + 393216] = z;

    const bool isX = blockIdx.x < 512;
    s_lut[tid] = isX ? vmap[tid] : wmap[tid];
    __syncthreads();

    unsigned hi[8], lo[8];
    if (isX) {
        const int b = blockIdx.x;
        const int r = b >> 3, m0b = (b & 7) * 256;
        const int m = m0b + tid;
        const float* src = X + (size_t)m * K_DIM + r * 16;
        float xs[16];
        ((float4*)xs)[0] = ((const float4*)src)[0];
        ((float4*)xs)[1] = ((const float4*)src)[1];
        ((float4*)xs)[2] = ((const float4*)src)[2];
        ((float4*)xs)[3] = ((const float4*)src)[3];
#pragma unroll
        for (int jj = 0; jj < 8; jj++) {
            unsigned short h[2], l[2];
#pragma unroll
            for (int e = 0; e < 2; e++) {
                int j = 2 * jj + e;
                float xv = xs[j];
                int idx = (int)(xv + 8.0f);
                idx = idx < 0 ? 0 : (idx > 15 ? 15 : idx);
                float xc = (xv + s_lut[j * 16 + idx]) * 0.0625f;
                __half hh = __float2half_rn(xc);
                __half ll = __float2half_rn(xc - __half2float(hh));
                h[e] = __half_as_ushort(hh);
                l[e] = __half_as_ushort(ll);
            }
            hi[jj] = h[0] | ((unsigned)h[1] << 16);
            lo[jj] = l[0] | ((unsigned)l[1] << 16);
        }
#pragma unroll
        for (int jj = 0; jj < 8; jj++) { sHi[tid][jj] = hi[jj]; sLo[tid][jj] = lo[jj]; }
        __syncthreads();

#pragma unroll
        for (int ss = 0; ss < 2; ss++) {
            int s = tid + 256 * ss;
            int f = s >> 5, l = s & 31, g = l >> 2, tq = l & 3;
            int r0 = f * 16 + g, r1 = r0 + 8;
            uint4 H = make_uint4(sHi[r0][tq], sHi[r1][tq], sHi[r0][tq + 4], sHi[r1][tq + 4]);
            uint4 L = make_uint4(sLo[r0][tq], sLo[r1][tq], sLo[r0][tq + 4], sLo[r1][tq + 4]);
            size_t gi = ((size_t)r * 128 + (m0b >> 4) + f) * 32 + l;
            g_Ahi[gi] = H;
            g_Alo[gi] = L;
        }
    } else {
        const int b = blockIdx.x - 512;
        const int r = b >> 2, n0b = (b & 3) * 256;
        const int n = n0b + tid;
#pragma unroll
        for (int jj = 0; jj < 8; jj++) {
            unsigned short h[2], l[2];
#pragma unroll
            for (int e = 0; e < 2; e++) {
                int j = 2 * jj + e;
                float w = W[(size_t)(16 * r + j) * N_DIM + n];
                int idx = (int)(w + 8.0f);
                idx = idx < 0 ? 0 : (idx > 15 ? 15 : idx);
                float wc = w + s_lut[j * 16 + idx];
                __half hh = __float2half_rn(wc);
                __half ll = __float2half_rn(wc - __half2float(hh));
                h[e] = __half_as_ushort(hh);
                l[e] = __half_as_ushort(ll);
            }
            hi[jj] = h[0] | ((unsigned)h[1] << 16);
            lo[jj] = l[0] | ((unsigned)l[1] << 16);
        }
#pragma unroll
        for (int jj = 0; jj < 8; jj++) { sHi[tid][jj] = hi[jj]; sLo[tid][jj] = lo[jj]; }
        __syncthreads();

#pragma unroll
        for (int ss = 0; ss < 4; ss++) {
            int s = tid + 256 * ss;
            int f = s >> 5, l = s & 31, g = l >> 2, tq = l & 3;
            int nl = f * 8 + g;
            uint4 V = make_uint4(sHi[nl][tq], sHi[nl][tq + 4], sLo[nl][tq], sLo[nl][tq + 4]);
            g_Bfr[((size_t)r * 128 + (n0b >> 3) + f) * 32 + l] = V;
        }
    }
}

// ---------------------------------------------------------------------------
#define MMA_INIT(C, A, B0, B1, Z)                                              \
    asm("mma.sync.aligned.m16n8k16.row.col.f32.f16.f16.f32 "                   \
        "{%0,%1,%2,%3}, {%4,%5,%6,%7}, {%8,%9}, {%10,%10,%10,%10};"            \
        : "=f"((C)[0]), "=f"((C)[1]), "=f"((C)[2]), "=f"((C)[3])               \
        : "r"((A).x), "r"((A).y), "r"((A).z), "r"((A).w), "r"(B0), "r"(B1),    \
          "f"(Z))

#define MMA_ACC(C, A, B0, B1)                                                  \
    asm("mma.sync.aligned.m16n8k16.row.col.f32.f16.f16.f32 "                   \
        "{%0,%1,%2,%3}, {%4,%5,%6,%7}, {%8,%9}, {%0,%1,%2,%3};"                \
        : "+f"((C)[0]), "+f"((C)[1]), "+f"((C)[2]), "+f"((C)[3])               \
        : "r"((A).x), "r"((A).y), "r"((A).z), "r"((A).w), "r"(B0), "r"(B1))

// ---------------------------------------------------------------------------
// Main: 444 CTAs, 3/SM (24 warps). CTA c runs jobs {c, c+444, c+888 if c<136};
// job = (tile, 16-chunk quarter). Single-buffered fragment loads; packed
// 16-bit su pairs (PRMT); atomic flush of exact integers. R8 chunk math.
// ---------------------------------------------------------------------------
__global__ void __launch_bounds__(256, 3)
opu_main_kernel(float* __restrict__ out) {
    const int t = threadIdx.x, wid = t >> 5, lane = t & 31;
    const int wm = (wid >> 1) * 32, wn = (wid & 1) * 32;
    const int c = blockIdx.x;
    const int njobs = (c < 136) ? 3 : 2;

    const float FZ = 0.0f;
    const float MAGIC2 = 12583040.0f;   // 1.5*2^23 + 128 (per-chunk +128 bias)
    const size_t CSTR = 128 * 32;

    for (int jj = 0; jj < njobs; jj++) {
        const int job = c + jj * NCTA_MAIN;
        const int tile = job >> 2;
        const int c0 = (job & 3) * 16;

        const int m0 = (tile >> 4) * 128, n0 = (tile & 15) * 64;
        const int mf = (m0 + wm) >> 4;
        const int nf = (n0 + wn) >> 3;
        const uint4* pA0 = g_Ahi + (size_t)mf * 32 + lane;
        const uint4* pA1 = g_Alo + (size_t)mf * 32 + lane;
        const uint4* pB  = g_Bfr + (size_t)nf * 32 + lane;

        // packed su: [i][j][p] p=0 -> (e0,e1) row g; p=1 -> (e2,e3) row g+8
        unsigned su[2][4][2];
#pragma unroll
        for (int i = 0; i < 2; i++)
#pragma unroll
            for (int j = 0; j < 4; j++) { su[i][j][0] = 0u; su[i][j][1] = 0u; }

#pragma unroll 2
        for (int r = 0; r < 16; r++) {
            const size_t o = (size_t)(c0 + r) * CSTR;
            uint4 AH0 = pA0[o], AH1 = pA0[o + 32];
            uint4 AL0 = pA1[o], AL1 = pA1[o + 32];
            uint4 B0 = pB[o], B1 = pB[o + 32], B2 = pB[o + 64], B3 = pB[o + 96];
            uint4 AH[2] = {AH0, AH1}, AL[2] = {AL0, AL1};
            uint4 BB[4] = {B0, B1, B2, B3};

#pragma unroll
            for (int i = 0; i < 2; i++)
#pragma unroll
                for (int jp = 0; jp < 2; jp++) {
                    float a0[4], a1[4];
                    const uint4 b0 = BB[2 * jp], b1 = BB[2 * jp + 1];
                    MMA_INIT(a0, AH[i], b0.x, b0.y, FZ);   // hi*whi
                    MMA_INIT(a1, AH[i], b1.x, b1.y, FZ);
                    MMA_ACC(a0, AH[i], b0.z, b0.w);        // hi*wlo
                    MMA_ACC(a1, AH[i], b1.z, b1.w);
                    MMA_ACC(a0, AL[i], b0.x, b0.y);        // lo*whi
                    MMA_ACC(a1, AL[i], b1.x, b1.y);
                    // RNE via magic(+128); pack two 16-bit codes per PRMT
                    unsigned q0 = __float_as_uint(a0[0] + MAGIC2);
                    unsigned q1 = __float_as_uint(a0[1] + MAGIC2);
                    unsigned q2 = __float_as_uint(a0[2] + MAGIC2);
                    unsigned q3 = __float_as_uint(a0[3] + MAGIC2);
                    su[i][2 * jp][0] += __byte_perm(q0, q1, 0x5410);
                    su[i][2 * jp][1] += __byte_perm(q2, q3, 0x5410);
                    unsigned p0 = __float_as_uint(a1[0] + MAGIC2);
                    unsigned p1 = __float_as_uint(a1[1] + MAGIC2);
                    unsigned p2 = __float_as_uint(a1[2] + MAGIC2);
                    unsigned p3 = __float_as_uint(a1[3] + MAGIC2);
                    su[i][2 * jp + 1][0] += __byte_perm(p0, p1, 0x5410);
                    su[i][2 * jp + 1][1] += __byte_perm(p2, p3, 0x5410);
                }
        }

        // flush: each half holds sum(code)+16*128; value = half - 2048
        const int g = lane >> 2, tg = lane & 3;
#pragma unroll
        for (int i = 0; i < 2; i++)
#pragma unroll
            for (int p = 0; p < 2; p++) {
                int row = m0 + wm + 16 * i + 8 * p + g;
                float* orow = out + (size_t)row * N_DIM + n0 + wn + 2 * tg;
#pragma unroll
                for (int j = 0; j < 4; j++) {
                    unsigned s = su[i][j][p];
                    atomicAdd(orow + 8 * j,
                              16.0f * (float)((int)(s & 0xFFFFu) - 2048));
                    atomicAdd(orow + 8 * j + 1,
                              16.0f * (float)((int)(s >> 16) - 2048));
                }
            }
    }
}

// ---------------------------------------------------------------------------
extern "C" void kernel_launch(void* const* d_in, const int* in_sizes, int n_in,
                              void* d_out, int out_size) {
    const float* X    = (const float*)d_in[0];  // (2,1024,1024)
    const float* W    = (const float*)d_in[1];  // (1024,1024)
    const float* vmap = (const float*)d_in[2];  // (16,16)
    const float* wmap = (const float*)d_in[3];  // (16,16)
    float* out = (float*)d_out;                 // (2,1024,1024)

    prep_kernel<<<768, 256>>>(X, W, vmap, wmap, (float4*)out);
    opu_main_kernel<<<NCTA_MAIN, 256>>>(out);
}

// round 16
// speedup vs baseline: 1.1191x; 1.0445x over previous
#include <cuda_runtime.h>
#include <cuda_fp16.h>
#include <cstdint>

#define K_DIM 1024
#define M_DIM 2048
#define N_DIM 1024
#define NCHUNK 64
#define NCTA_MAIN 888   // 6 per SM exactly

// fp16 split planes, 64 B per row: A=[hi(32B)|lo(32B)], B=[whi(32B)|wlo(32B)]
__device__ __half g_A[(size_t)NCHUNK * M_DIM * 32];
__device__ __half g_B[(size_t)NCHUNK * N_DIM * 32];

// ---------------------------------------------------------------------------
// Fused prep (R6 layout) + output zeroing folded in. 768 blocks x 256.
// ---------------------------------------------------------------------------
__global__ void prep_kernel(const float* __restrict__ X,
                            const float* __restrict__ W,
                            const float* __restrict__ vmap,
                            const float* __restrict__ wmap,
                            float4* __restrict__ outz) {
    __shared__ float s_lut[256];
    const int tid = threadIdx.x;
    const int gid = blockIdx.x * 256 + tid;
    const float4 z = make_float4(0.f, 0.f, 0.f, 0.f);
    outz[gid] = z;
    outz[gid + 196608] = z;
    if (gid + 393216 < 524288) outz[gid + 393216] = z;

    const bool isX = blockIdx.x < 512;
    s_lut[tid] = isX ? vmap[tid] : wmap[tid];
    __syncthreads();

    if (isX) {
        int g2 = blockIdx.x * 256 + tid;
        int r = g2 >> 11, m = g2 & 2047;
        const float* src = X + (size_t)m * K_DIM + r * 16;
        float xs[16];
        ((float4*)xs)[0] = ((const float4*)src)[0];
        ((float4*)xs)[1] = ((const float4*)src)[1];
        ((float4*)xs)[2] = ((const float4*)src)[2];
        ((float4*)xs)[3] = ((const float4*)src)[3];
        unsigned hi[8], lo[8];
#pragma unroll
        for (int jj = 0; jj < 8; jj++) {
            unsigned short h[2], l[2];
#pragma unroll
            for (int e = 0; e < 2; e++) {
                int j = 2 * jj + e;
                float xv = xs[j];
                int idx = (int)(xv + 8.0f);
                idx = idx < 0 ? 0 : (idx > 15 ? 15 : idx);
                float xc = (xv + s_lut[j * 16 + idx]) * 0.0625f;
                __half hh = __float2half_rn(xc);
                __half ll = __float2half_rn(xc - __half2float(hh));
                h[e] = __half_as_ushort(hh);
                l[e] = __half_as_ushort(ll);
            }
            hi[jj] = h[0] | ((unsigned)h[1] << 16);
            lo[jj] = l[0] | ((unsigned)l[1] << 16);
        }
        uint4* dst = (uint4*)(g_A + ((size_t)r * M_DIM + m) * 32);
        dst[0] = make_uint4(hi[0], hi[1], hi[2], hi[3]);
        dst[1] = make_uint4(hi[4], hi[5], hi[6], hi[7]);
        dst[2] = make_uint4(lo[0], lo[1], lo[2], lo[3]);
        dst[3] = make_uint4(lo[4], lo[5], lo[6], lo[7]);
    } else {
        int idx4 = blockIdx.x - 512;
        int r = idx4 >> 2;
        int n = (idx4 & 3) * 256 + tid;
        unsigned hi[8], lo[8];
#pragma unroll
        for (int jj = 0; jj < 8; jj++) {
            unsigned short h[2], l[2];
#pragma unroll
            for (int e = 0; e < 2; e++) {
                int j = 2 * jj + e;
                float w = W[(size_t)(16 * r + j) * N_DIM + n];
                int idx = (int)(w + 8.0f);
                idx = idx < 0 ? 0 : (idx > 15 ? 15 : idx);
                float wc = w + s_lut[j * 16 + idx];
                __half hh = __float2half_rn(wc);
                __half ll = __float2half_rn(wc - __half2float(hh));
                h[e] = __half_as_ushort(hh);
                l[e] = __half_as_ushort(ll);
            }
            hi[jj] = h[0] | ((unsigned)h[1] << 16);
            lo[jj] = l[0] | ((unsigned)l[1] << 16);
        }
        uint4* dst = (uint4*)(g_B + ((size_t)r * N_DIM + n) * 32);
        dst[0] = make_uint4(hi[0], hi[1], hi[2], hi[3]);
        dst[1] = make_uint4(hi[4], hi[5], hi[6], hi[7]);
        dst[2] = make_uint4(lo[0], lo[1], lo[2], lo[3]);
        dst[3] = make_uint4(lo[4], lo[5], lo[6], lo[7]);
    }
}

// ---------------------------------------------------------------------------
#define LDSM4(R, addr)                                                         \
    asm volatile("ldmatrix.sync.aligned.m8n8.x4.shared.b16 {%0,%1,%2,%3}, [%4];" \
                 : "=r"((R)[0]), "=r"((R)[1]), "=r"((R)[2]), "=r"((R)[3])      \
                 : "r"(addr))

#define MMA_I(C, A, B0, B1)                                                    \
    asm("mma.sync.aligned.m16n8k16.row.col.f32.f16.f16.f32 "                   \
        "{%0,%1,%2,%3}, {%4,%5,%6,%7}, {%8,%9}, {%10,%10,%10,%10};"            \
        : "=f"((C)[0]), "=f"((C)[1]), "=f"((C)[2]), "=f"((C)[3])               \
        : "r"((A)[0]), "r"((A)[1]), "r"((A)[2]), "r"((A)[3]), "r"(B0), "r"(B1),\
          "f"(0.0f))

#define MMA_A(C, A, B0, B1)                                                    \
    asm("mma.sync.aligned.m16n8k16.row.col.f32.f16.f16.f32 "                   \
        "{%0,%1,%2,%3}, {%4,%5,%6,%7}, {%8,%9}, {%0,%1,%2,%3};"                \
        : "+f"((C)[0]), "+f"((C)[1]), "+f"((C)[2]), "+f"((C)[3])               \
        : "r"((A)[0]), "r"((A)[1]), "r"((A)[2]), "r"((A)[3]), "r"(B0), "r"(B1))

// swizzled smem offset for (row, 16-B granule c in 0..3), 64-B logical rows
__device__ __forceinline__ unsigned phys(int row, int c) {
    return ((unsigned)(row >> 1) << 7) + ((unsigned)(row & 1) << 6) +
           (((unsigned)(c ^ ((row >> 1) & 3))) << 4);
}

// stage layout: [A(even) 4K | A(odd) 4K | B(even) 4K | B(odd) 4K] = 16 KB
#define STG 16384u

// ---------------------------------------------------------------------------
// Main: 888 CTAs x 128 thr (6/SM, 24 warps/SM). Job = (64x64 tile, 32 chunks);
// CTA c runs job c (+ job 888+c if c<136). cp.async 2-stage pair pipeline,
// packed 16-bit su, atomicAdd flush of exact integers.
// ---------------------------------------------------------------------------
__global__ void __launch_bounds__(128, 6)
opu_main_kernel(float* __restrict__ out) {
    __shared__ __align__(1024) char smem[2 * STG];
    const unsigned sb0 = (unsigned)__cvta_generic_to_shared(smem);

    const int t = threadIdx.x, wid = t >> 5, lane = t & 31;
    const int wm = (wid >> 1) * 32, wn = (wid & 1) * 32;

    // staging geometry: per chunk 256 A granules + 256 B granules; 128 threads
    const int arow0 = t >> 2, col = t & 3;        // rows 0..31
    const int arow1 = 32 + arow0;                 // rows 32..63
    const unsigned d0 = phys(arow0, col), d1 = phys(arow1, col);

    // ldmatrix addresses
    const int l15 = lane & 15, lhi = lane >> 4;
    const int l7 = lane & 7, lq = lane >> 3;
    unsigned ahi_ad[2], alo_ad[2], b_ad[4];
#pragma unroll
    for (int i = 0; i < 2; i++) {
        int row = wm + 16 * i + l15;
        ahi_ad[i] = phys(row, lhi);
        alo_ad[i] = phys(row, 2 + lhi);
    }
#pragma unroll
    for (int j = 0; j < 4; j++) {
        int row = wn + 8 * j + l7;
        b_ad[j] = phys(row, lq);
    }

    const char* gA = (const char*)g_A;
    const char* gB = (const char*)g_B;
    const float MAGIC2 = 12583040.0f;   // 1.5*2^23 + 128

    const int c = blockIdx.x;
    const int njobs = (c < 136) ? 2 : 1;

    for (int jj = 0; jj < njobs; jj++) {
        const int job = c + jj * NCTA_MAIN;
        const int tile = job >> 1;
        const int c0 = (job & 1) * 32;
        const int m0 = (tile >> 4) * 64, n0 = (tile & 15) * 64;

#define CPA(dst, src) asm volatile("cp.async.cg.shared.global [%0], [%1], 16;" :: "r"(dst), "l"(src))
#define STAGE_PAIR(p, s)                                                       \
        do {                                                                   \
            int ch0 = c0 + 2 * (p), ch1 = ch0 + 1;                             \
            unsigned base = sb0 + (unsigned)(s) * STG;                         \
            CPA(base + d0, gA + ((size_t)ch0 * M_DIM + m0 + arow0) * 64 + col * 16); \
            CPA(base + d1, gA + ((size_t)ch0 * M_DIM + m0 + arow1) * 64 + col * 16); \
            CPA(base + 4096u + d0, gA + ((size_t)ch1 * M_DIM + m0 + arow0) * 64 + col * 16); \
            CPA(base + 4096u + d1, gA + ((size_t)ch1 * M_DIM + m0 + arow1) * 64 + col * 16); \
            CPA(base + 8192u + d0, gB + ((size_t)ch0 * N_DIM + n0 + arow0) * 64 + col * 16); \
            CPA(base + 8192u + d1, gB + ((size_t)ch0 * N_DIM + n0 + arow1) * 64 + col * 16); \
            CPA(base + 12288u + d0, gB + ((size_t)ch1 * N_DIM + n0 + arow0) * 64 + col * 16); \
            CPA(base + 12288u + d1, gB + ((size_t)ch1 * N_DIM + n0 + arow1) * 64 + col * 16); \
            asm volatile("cp.async.commit_group;");                            \
        } while (0)

#define COMPUTE_CHUNK(ab, bb)                                                  \
        do {                                                                   \
            unsigned bfr[4][4], ah[2][4], al[2][4];                            \
            _Pragma("unroll")                                                  \
            for (int j = 0; j < 4; j++) LDSM4(bfr[j], (bb) + b_ad[j]);         \
            _Pragma("unroll")                                                  \
            for (int i = 0; i < 2; i++) LDSM4(ah[i], (ab) + ahi_ad[i]);        \
            _Pragma("unroll")                                                  \
            for (int i = 0; i < 2; i++) LDSM4(al[i], (ab) + alo_ad[i]);        \
            _Pragma("unroll")                                                  \
            for (int i = 0; i < 2; i++)                                        \
                _Pragma("unroll")                                              \
                for (int jp = 0; jp < 2; jp++) {                               \
                    float a0[4], a1[4];                                        \
                    MMA_I(a0, ah[i], bfr[2 * jp][0], bfr[2 * jp][1]);          \
                    MMA_I(a1, ah[i], bfr[2 * jp + 1][0], bfr[2 * jp + 1][1]);  \
                    MMA_A(a0, ah[i], bfr[2 * jp][2], bfr[2 * jp][3]);          \
                    MMA_A(a1, ah[i], bfr[2 * jp + 1][2], bfr[2 * jp + 1][3]);  \
                    MMA_A(a0, al[i], bfr[2 * jp][0], bfr[2 * jp][1]);          \
                    MMA_A(a1, al[i], bfr[2 * jp + 1][0], bfr[2 * jp + 1][1]);  \
                    unsigned q0 = __float_as_uint(a0[0] + MAGIC2);             \
                    unsigned q1 = __float_as_uint(a0[1] + MAGIC2);             \
                    unsigned q2 = __float_as_uint(a0[2] + MAGIC2);             \
                    unsigned q3 = __float_as_uint(a0[3] + MAGIC2);             \
                    su[i][2 * jp][0] += __byte_perm(q0, q1, 0x5410);           \
                    su[i][2 * jp][1] += __byte_perm(q2, q3, 0x5410);           \
                    unsigned p0 = __float_as_uint(a1[0] + MAGIC2);             \
                    unsigned p1 = __float_as_uint(a1[1] + MAGIC2);             \
                    unsigned p2 = __float_as_uint(a1[2] + MAGIC2);             \
                    unsigned p3 = __float_as_uint(a1[3] + MAGIC2);             \
                    su[i][2 * jp + 1][0] += __byte_perm(p0, p1, 0x5410);       \
                    su[i][2 * jp + 1][1] += __byte_perm(p2, p3, 0x5410);       \
                }                                                              \
        } while (0)

        unsigned su[2][4][2];
#pragma unroll
        for (int i = 0; i < 2; i++)
#pragma unroll
            for (int j = 0; j < 4; j++) { su[i][j][0] = 0u; su[i][j][1] = 0u; }

        STAGE_PAIR(0, 0);
        for (int p = 0; p < 16; p++) {
            asm volatile("cp.async.wait_group 0;" ::: "memory");
            __syncthreads();
            if (p + 1 < 16) STAGE_PAIR(p + 1, (p + 1) & 1);
            const unsigned base = sb0 + (unsigned)(p & 1) * STG;
            COMPUTE_CHUNK(base, base + 8192u);
            COMPUTE_CHUNK(base + 4096u, base + 12288u);
        }

        // flush: half-word = sum(code) + 32*128; value = 16*(half - 4096)
        const int g = lane >> 2, tg = lane & 3;
#pragma unroll
        for (int i = 0; i < 2; i++)
#pragma unroll
            for (int pp = 0; pp < 2; pp++) {
                int row = m0 + wm + 16 * i + 8 * pp + g;
                float* orow = out + (size_t)row * N_DIM + n0 + wn + 2 * tg;
#pragma unroll
                for (int j = 0; j < 4; j++) {
                    unsigned s = su[i][j][pp];
                    atomicAdd(orow + 8 * j,
                              16.0f * (float)((int)(s & 0xFFFFu) - 4096));
                    atomicAdd(orow + 8 * j + 1,
                              16.0f * (float)((int)(s >> 16) - 4096));
                }
            }
#undef STAGE_PAIR
#undef COMPUTE_CHUNK
#undef CPA
    }
}

// ---------------------------------------------------------------------------
extern "C" void kernel_launch(void* const* d_in, const int* in_sizes, int n_in,
                              void* d_out, int out_size) {
    const float* X    = (const float*)d_in[0];  // (2,1024,1024)
    const float* W    = (const float*)d_in[1];  // (1024,1024)
    const float* vmap = (const float*)d_in[2];  // (16,16)
    const float* wmap = (const float*)d_in[3];  // (16,16)
    float* out = (float*)d_out;                 // (2,1024,1024)

    prep_kernel<<<768, 256>>>(X, W, vmap, wmap, (float4*)out);
    opu_main_kernel<<<NCTA_MAIN, 128>>>(out);
}